// round 3
// baseline (speedup 1.0000x reference)
#include <cuda_runtime.h>

#define HDIM   96
#define NPIX   9216          // 96*96
#define NC     21
#define NC2    22            // +1 "ones" channel for the bilateral normalizer
#define NB     2
#define SPLITS 16
#define JLEN   (NPIX / SPLITS)   // 576
#define JCHUNK 96
#define NCHUNK (JLEN / JCHUNK)   // 6
#define ITILE  1024              // output columns per gemm block (256 thr * 4)

// ---------------- device globals (no cudaMalloc allowed) ----------------
__device__ float g_Kb[(size_t)NB * NPIX * NPIX];           // 679 MB bilateral kernel
__device__ float g_u [NB * NC  * NPIX];
__device__ float g_q [NB * NC  * NPIX];
__device__ float g_sm[NB * NC2 * NPIX];                    // softmax + ones channel
__device__ float g_t1[NB * NC  * NPIX];                    // x-blur temp
__device__ float g_sp[NB * NC  * NPIX];                    // spatial-filtered
__device__ float g_part[(size_t)SPLITS * NB * NC2 * NPIX]; // split-K partials (26 MB)
__device__ float g_gk[HDIM];                               // exp(-d^2/18)
__device__ float g_snrow[HDIM];                            // separable spatial norm
__device__ float g_A1[NC * NC];                            // M @ Ws
__device__ float g_A2[NC * NC];                            // M @ Wb

// packed f32x2 FMA (Blackwell): d = a*b + c lanewise on .b64
__device__ __forceinline__ unsigned long long ffma2(unsigned long long a,
                                                    unsigned long long b,
                                                    unsigned long long c) {
    unsigned long long d;
    asm("fma.rn.f32x2 %0, %1, %2, %3;" : "=l"(d) : "l"(a), "l"(b), "l"(c));
    return d;
}

// ---------------- init: spatial 1-D kernel table + separable norm ----------------
__global__ void k_tables() {
    int t = threadIdx.x;                       // 96 threads
    g_gk[t] = __expf(-(float)(t * t) * (1.0f / 18.0f));
    __syncthreads();
    float s = 0.0f;
    for (int y2 = 0; y2 < HDIM; y2++) s += g_gk[abs(t - y2)];
    g_snrow[t] = s;
}

// A1 = M@Ws, A2 = M@Wb  (fold compatibility transform into message weights)
__global__ void k_mm(const float* __restrict__ Wsp, const float* __restrict__ Wbp,
                     const float* __restrict__ Mp) {
    int t = threadIdx.x;
    if (t >= NC * NC) return;
    int c = t / NC, c2 = t % NC;
    float a1 = 0.0f, a2 = 0.0f;
    for (int k = 0; k < NC; k++) {
        float m = Mp[c * NC + k];
        a1 += m * Wsp[k * NC + c2];
        a2 += m * Wbp[k * NC + c2];
    }
    g_A1[t] = a1;
    g_A2[t] = a2;
}

// unary [B,H,W,C] -> u,q [B,C,N]
__global__ void k_init_u(const float* __restrict__ unary) {
    int t = blockIdx.x * blockDim.x + threadIdx.x;
    if (t >= NB * NC * NPIX) return;
    int n = t % NPIX;
    int bc = t / NPIX;
    int c = bc % NC, b = bc / NC;
    float v = unary[((size_t)(b * NPIX + n)) * NC + c];
    g_u[t] = v;
    g_q[t] = v;
}

// ---------------- build dense bilateral kernel Kb ----------------
// tile: 256 i-columns (thread) x 32 j-rows (loop); writes Kb[b][j*N + i] coalesced.
__global__ __launch_bounds__(256) void k_build(const float* __restrict__ rgb) {
    __shared__ float sjf[5][32];
    int b  = blockIdx.z;
    int i  = blockIdx.x * 256 + threadIdx.x;
    int j0 = blockIdx.y * 32;
    if (threadIdx.x < 32) {
        int j = j0 + threadIdx.x;
        const float* rp = rgb + ((size_t)(b * NPIX + j)) * 3;
        sjf[0][threadIdx.x] = (float)(j / HDIM) * (1.0f / 160.0f);
        sjf[1][threadIdx.x] = (float)(j % HDIM) * (1.0f / 160.0f);
        sjf[2][threadIdx.x] = rp[0] * (1.0f / 3.0f);
        sjf[3][threadIdx.x] = rp[1] * (1.0f / 3.0f);
        sjf[4][threadIdx.x] = rp[2] * (1.0f / 3.0f);
    }
    __syncthreads();
    const float* rp = rgb + ((size_t)(b * NPIX + i)) * 3;
    float yi = (float)(i / HDIM) * (1.0f / 160.0f);
    float xi = (float)(i % HDIM) * (1.0f / 160.0f);
    float ri = rp[0] * (1.0f / 3.0f);
    float gi = rp[1] * (1.0f / 3.0f);
    float bi = rp[2] * (1.0f / 3.0f);
    float* out = g_Kb + (size_t)b * NPIX * NPIX + (size_t)j0 * NPIX + i;
#pragma unroll 4
    for (int jj = 0; jj < 32; jj++) {
        float dy = yi - sjf[0][jj];
        float dx = xi - sjf[1][jj];
        float dr = ri - sjf[2][jj];
        float dg = gi - sjf[3][jj];
        float db = bi - sjf[4][jj];
        float d2 = dy * dy + dx * dx + dr * dr + dg * dg + db * db;
        out[(size_t)jj * NPIX] = __expf(-0.5f * d2);
    }
}

// ---------------- per-iteration kernels ----------------
__global__ void k_softmax() {
    int t = blockIdx.x * blockDim.x + threadIdx.x;
    if (t >= NB * NPIX) return;
    int b = t / NPIX, n = t % NPIX;
    const float* q = g_q + (size_t)b * NC * NPIX + n;
    float v[NC];
    float mx = -1e30f;
#pragma unroll
    for (int c = 0; c < NC; c++) { v[c] = q[c * NPIX]; mx = fmaxf(mx, v[c]); }
    float s = 0.0f;
#pragma unroll
    for (int c = 0; c < NC; c++) { v[c] = __expf(v[c] - mx); s += v[c]; }
    float inv = 1.0f / s;
    float* o = g_sm + (size_t)b * NC2 * NPIX + n;
#pragma unroll
    for (int c = 0; c < NC; c++) o[c * NPIX] = v[c] * inv;
    o[NC * NPIX] = 1.0f;  // ones channel -> bilateral norm via the same GEMM
}

// separable spatial filtering: x pass then y pass (exact 96-tap Gaussian)
__global__ void k_convx() {
    __shared__ float srow[HDIM], sg[HDIM];
    int r = blockIdx.x;            // (b*NC + c)*HDIM + y
    int t = threadIdx.x;           // x
    int y = r % HDIM;
    int bc = r / HDIM;
    int c = bc % NC, b = bc / NC;
    srow[t] = g_sm[((size_t)(b * NC2 + c)) * NPIX + y * HDIM + t];
    sg[t] = g_gk[t];
    __syncthreads();
    float s = 0.0f;
#pragma unroll 8
    for (int xp = 0; xp < HDIM; xp++) s += srow[xp] * sg[abs(t - xp)];
    g_t1[(size_t)bc * NPIX + y * HDIM + t] = s;
}

__global__ void k_convy() {
    __shared__ float sg[HDIM];
    int r = blockIdx.x;            // (b*NC + c)*HDIM + y_out
    int t = threadIdx.x;           // x
    int yo = r % HDIM;
    int bc = r / HDIM;
    sg[t] = g_gk[t];
    __syncthreads();
    const float* in = g_t1 + (size_t)bc * NPIX + t;
    float s = 0.0f;
#pragma unroll 8
    for (int yp = 0; yp < HDIM; yp++) s += in[yp * HDIM] * sg[abs(yo - yp)];
    g_sp[(size_t)bc * NPIX + yo * HDIM + t] = s;
}

// ---------------- the big one: bl_part[s][b][c][i] = sum_{j in split s} sm[c,j]*Kb[j,i]
// block: 256 threads, 4 cols/thread (1024 cols), split-K over 16 j-ranges, 2 batches.
// inner loop per j: 1 LDG.128 of Kb + 22 broadcast LDS.64 of pre-packed {v,v} sm + 44 FFMA2.
__global__ __launch_bounds__(256, 2) void k_gemm() {
    __shared__ unsigned long long s_pk[NC2 * JCHUNK];  // 16.9 KB
    int i0 = blockIdx.x * ITILE + threadIdx.x * 4;
    int sp = blockIdx.y;
    int b  = blockIdx.z;
    const float* kb_base = g_Kb + (size_t)b * NPIX * NPIX;
    unsigned long long acc[NC2][2];
#pragma unroll
    for (int c = 0; c < NC2; c++) { acc[c][0] = 0ull; acc[c][1] = 0ull; }
    int jbase0 = sp * JLEN;
    for (int ch = 0; ch < NCHUNK; ch++) {
        int jbase = jbase0 + ch * JCHUNK;
        __syncthreads();
        for (int idx = threadIdx.x; idx < NC2 * JCHUNK; idx += 256) {
            int c = idx / JCHUNK, jj = idx % JCHUNK;
            unsigned int bits =
                __float_as_uint(g_sm[((size_t)(b * NC2 + c)) * NPIX + jbase + jj]);
            s_pk[idx] = ((unsigned long long)bits << 32) | bits;  // {v, v}
        }
        __syncthreads();
        const float* p = kb_base + (size_t)jbase * NPIX + i0;
#pragma unroll 2
        for (int jj = 0; jj < JCHUNK; jj++) {
            ulonglong2 kb = *reinterpret_cast<const ulonglong2*>(p);
            p += NPIX;
#pragma unroll
            for (int c = 0; c < NC2; c++) {
                unsigned long long sv = s_pk[c * JCHUNK + jj];
                acc[c][0] = ffma2(sv, kb.x, acc[c][0]);
                acc[c][1] = ffma2(sv, kb.y, acc[c][1]);
            }
        }
    }
#pragma unroll
    for (int c = 0; c < NC2; c++) {
        float4 v;
        v.x = __uint_as_float((unsigned)(acc[c][0]));
        v.y = __uint_as_float((unsigned)(acc[c][0] >> 32));
        v.z = __uint_as_float((unsigned)(acc[c][1]));
        v.w = __uint_as_float((unsigned)(acc[c][1] >> 32));
        *reinterpret_cast<float4*>(
            &g_part[(((size_t)sp * NB + b) * NC2 + c) * NPIX + i0]) = v;
    }
}

// reduce split-K partials, normalize, apply folded message weights, update q
__global__ __launch_bounds__(256) void k_update() {
    __shared__ float sA1[NC * NC], sA2[NC * NC];
    for (int i = threadIdx.x; i < NC * NC; i += 256) { sA1[i] = g_A1[i]; sA2[i] = g_A2[i]; }
    __syncthreads();
    int t = blockIdx.x * 256 + threadIdx.x;  // 0 .. 2N-1, N divisible by 256
    int b = t / NPIX, n = t % NPIX;
    float bl[NC];
    float bn = 0.0f;
#pragma unroll
    for (int c = 0; c < NC; c++) bl[c] = 0.0f;
    for (int s = 0; s < SPLITS; s++) {
        const float* pp = g_part + ((size_t)(s * NB + b)) * NC2 * NPIX + n;
#pragma unroll
        for (int c = 0; c < NC; c++) bl[c] += pp[c * NPIX];
        bn += pp[NC * NPIX];
    }
    float inv_bn = 1.0f / bn;
    float inv_sn = 1.0f / (g_snrow[n / HDIM] * g_snrow[n % HDIM]);
    float spv[NC];
    const float* spp = g_sp + (size_t)b * NC * NPIX + n;
#pragma unroll
    for (int c = 0; c < NC; c++) {
        spv[c] = spp[c * NPIX] * inv_sn;
        bl[c] *= inv_bn;
    }
    const float* up = g_u + (size_t)b * NC * NPIX + n;
    float* qp = g_q + (size_t)b * NC * NPIX + n;
    for (int c = 0; c < NC; c++) {
        float a = up[c * NPIX];
#pragma unroll
        for (int c2 = 0; c2 < NC; c2++)
            a -= sA1[c * NC + c2] * spv[c2] + sA2[c * NC + c2] * bl[c2];
        qp[c * NPIX] = a;
    }
}

// q [B,C,N] -> out [B,H,W,C]
__global__ void k_final(float* __restrict__ out) {
    int t = blockIdx.x * blockDim.x + threadIdx.x;
    if (t >= NB * NPIX * NC) return;
    int c = t % NC;
    int bn_ = t / NC;
    int n = bn_ % NPIX, b = bn_ / NPIX;
    out[t] = g_q[((size_t)b * NC + c) * NPIX + n];
}

// ---------------- launch ----------------
extern "C" void kernel_launch(void* const* d_in, const int* in_sizes, int n_in,
                              void* d_out, int out_size) {
    const float* unary = (const float*)d_in[0];  // [2,96,96,21]
    const float* rgb   = (const float*)d_in[1];  // [2,96,96,3]
    const float* Wsp   = (const float*)d_in[2];  // [21,21]
    const float* Wbp   = (const float*)d_in[3];  // [21,21]
    const float* Mp    = (const float*)d_in[4];  // [21,21]

    k_tables<<<1, HDIM>>>();
    k_mm<<<1, 448>>>(Wsp, Wbp, Mp);
    k_init_u<<<(NB * NC * NPIX + 255) / 256, 256>>>(unary);
    k_build<<<dim3(NPIX / 256, NPIX / 32, NB), 256>>>(rgb);

    for (int it = 0; it < 5; it++) {
        k_softmax<<<(NB * NPIX + 255) / 256, 256>>>();
        k_convx<<<NB * NC * HDIM, HDIM>>>();
        k_convy<<<NB * NC * HDIM, HDIM>>>();
        k_gemm<<<dim3(NPIX / ITILE, SPLITS, NB), 256>>>();
        k_update<<<NB * NPIX / 256, 256>>>();
    }
    k_final<<<(NB * NPIX * NC + 255) / 256, 256>>>((float*)d_out);
}

// round 5
// speedup vs baseline: 1.0137x; 1.0137x over previous
#include <cuda_runtime.h>
#include <cuda_bf16.h>

#define HDIM   96
#define NPIX   9216          // 96*96
#define NC     21
#define NC2    22            // +1 "ones" channel for the bilateral normalizer
#define NB     2
#define SPLITS 16
#define JLEN   (NPIX / SPLITS)   // 576
#define JCHUNK 96
#define NCHUNK (JLEN / JCHUNK)   // 6
#define ITILE  1024              // output columns per gemm block (256 thr * 4)

// ---------------- device globals (no cudaMalloc allowed) ----------------
__device__ __nv_bfloat16 g_Kbh[(size_t)NB * NPIX * NPIX]; // 340 MB bilateral kernel (bf16)
__device__ float g_u [NB * NC  * NPIX];
__device__ float g_q [NB * NC  * NPIX];
__device__ float g_sm[NB * NC2 * NPIX];                    // softmax + ones channel
__device__ float g_t1[NB * NC  * NPIX];                    // x-blur temp
__device__ float g_sp[NB * NC  * NPIX];                    // spatial-filtered
__device__ float g_part[(size_t)SPLITS * NB * NC2 * NPIX]; // split-K partials (26 MB)
__device__ float g_gk[HDIM];                               // exp(-d^2/18)
__device__ float g_snrow[HDIM];                            // separable spatial norm
__device__ float g_A1[NC * NC];                            // M @ Ws
__device__ float g_A2[NC * NC];                            // M @ Wb

typedef unsigned long long u64;
typedef unsigned int u32;

// ---------------- packed f32x2 helpers (Blackwell) ----------------
__device__ __forceinline__ u64 ffma2(u64 a, u64 b, u64 c) {
    u64 d; asm("fma.rn.f32x2 %0, %1, %2, %3;" : "=l"(d) : "l"(a), "l"(b), "l"(c)); return d;
}
__device__ __forceinline__ u64 fadd2(u64 a, u64 b) {
    u64 d; asm("add.rn.f32x2 %0, %1, %2;" : "=l"(d) : "l"(a), "l"(b)); return d;
}
__device__ __forceinline__ u64 fmul2(u64 a, u64 b) {
    u64 d; asm("mul.rn.f32x2 %0, %1, %2;" : "=l"(d) : "l"(a), "l"(b)); return d;
}
__device__ __forceinline__ u64 pk2(float lo, float hi) {
    u64 r; asm("mov.b64 %0, {%1, %2};" : "=l"(r) : "f"(lo), "f"(hi)); return r;
}
__device__ __forceinline__ void upk2(u64 v, float& lo, float& hi) {
    asm("mov.b64 {%0, %1}, %2;" : "=f"(lo), "=f"(hi) : "l"(v));
}
__device__ __forceinline__ float ex2f(float x) {
    float y; asm("ex2.approx.f32 %0, %1;" : "=f"(y) : "f"(x)); return y;
}
// bf16x2 (u32) -> f32x2 (u64): lo half -> lo float, hi half -> hi float
__device__ __forceinline__ u64 bf2f2(u32 u) {
    u32 lo = u << 16;
    u32 hi = u & 0xFFFF0000u;
    u64 r; asm("mov.b64 %0, {%1, %2};" : "=l"(r) : "r"(lo), "r"(hi)); return r;
}
// two f32 -> bf16x2 (rn): a -> high, b -> low
__device__ __forceinline__ u32 f2bf2(float hi, float lo) {
    u32 r; asm("cvt.rn.bf16x2.f32 %0, %1, %2;" : "=r"(r) : "f"(hi), "f"(lo)); return r;
}

// ---------------- init: spatial 1-D kernel table + separable norm ----------------
__global__ void k_tables() {
    int t = threadIdx.x;                       // 96 threads
    g_gk[t] = __expf(-(float)(t * t) * (1.0f / 18.0f));
    __syncthreads();
    float s = 0.0f;
    for (int y2 = 0; y2 < HDIM; y2++) s += g_gk[abs(t - y2)];
    g_snrow[t] = s;
}

// A1 = M@Ws, A2 = M@Wb
__global__ void k_mm(const float* __restrict__ Wsp, const float* __restrict__ Wbp,
                     const float* __restrict__ Mp) {
    int t = threadIdx.x;
    if (t >= NC * NC) return;
    int c = t / NC, c2 = t % NC;
    float a1 = 0.0f, a2 = 0.0f;
    for (int k = 0; k < NC; k++) {
        float m = Mp[c * NC + k];
        a1 += m * Wsp[k * NC + c2];
        a2 += m * Wbp[k * NC + c2];
    }
    g_A1[t] = a1;
    g_A2[t] = a2;
}

// unary [B,H,W,C] -> u,q [B,C,N]
__global__ void k_init_u(const float* __restrict__ unary) {
    int t = blockIdx.x * blockDim.x + threadIdx.x;
    if (t >= NB * NC * NPIX) return;
    int n = t % NPIX;
    int bc = t / NPIX;
    int c = bc % NC, b = bc / NC;
    float v = unary[((size_t)(b * NPIX + n)) * NC + c];
    g_u[t] = v;
    g_q[t] = v;
}

// ---------------- build dense bilateral kernel Kb (bf16, packed f32x2 math) ----------------
// each thread handles an adjacent i-pair (i0, i0+1); 32 j-rows per block.
__global__ __launch_bounds__(256) void k_build(const float* __restrict__ rgb) {
    __shared__ u64 snj[5][32];   // NEGATED scaled j features, duplicated {-v,-v}
    int b  = blockIdx.z;
    int i0 = (blockIdx.x * 256 + threadIdx.x) * 2;
    int j0 = blockIdx.y * 32;
    if (threadIdx.x < 32) {
        int j = j0 + threadIdx.x;
        const float* rp = rgb + ((size_t)(b * NPIX + j)) * 3;
        float vy = -(float)(j / HDIM) * (1.0f / 160.0f);
        float vx = -(float)(j % HDIM) * (1.0f / 160.0f);
        float vr = -rp[0] * (1.0f / 3.0f);
        float vg = -rp[1] * (1.0f / 3.0f);
        float vb = -rp[2] * (1.0f / 3.0f);
        snj[0][threadIdx.x] = pk2(vy, vy);
        snj[1][threadIdx.x] = pk2(vx, vx);
        snj[2][threadIdx.x] = pk2(vr, vr);
        snj[3][threadIdx.x] = pk2(vg, vg);
        snj[4][threadIdx.x] = pk2(vb, vb);
    }
    __syncthreads();
    const float* rp0 = rgb + ((size_t)(b * NPIX + i0)) * 3;
    // packed i-pair features (i0 even -> i0, i0+1 always in the same image row)
    u64 fy = pk2((float)(i0 / HDIM) * (1.0f / 160.0f), (float)((i0 + 1) / HDIM) * (1.0f / 160.0f));
    u64 fx = pk2((float)(i0 % HDIM) * (1.0f / 160.0f), (float)((i0 + 1) % HDIM) * (1.0f / 160.0f));
    u64 fr = pk2(rp0[0] * (1.0f / 3.0f), rp0[3] * (1.0f / 3.0f));
    u64 fg = pk2(rp0[1] * (1.0f / 3.0f), rp0[4] * (1.0f / 3.0f));
    u64 fb = pk2(rp0[2] * (1.0f / 3.0f), rp0[5] * (1.0f / 3.0f));
    const float m05l2e = -0.7213475204444817f;       // -0.5 * log2(e)
    u64 cm = pk2(m05l2e, m05l2e);
    __nv_bfloat16* out = g_Kbh + (size_t)b * NPIX * NPIX + (size_t)j0 * NPIX + i0;
#pragma unroll 4
    for (int jj = 0; jj < 32; jj++) {
        u64 d, acc;
        d = fadd2(fy, snj[0][jj]); acc = fmul2(d, d);
        d = fadd2(fx, snj[1][jj]); acc = ffma2(d, d, acc);
        d = fadd2(fr, snj[2][jj]); acc = ffma2(d, d, acc);
        d = fadd2(fg, snj[3][jj]); acc = ffma2(d, d, acc);
        d = fadd2(fb, snj[4][jj]); acc = ffma2(d, d, acc);
        u64 arg = fmul2(acc, cm);
        float a0, a1; upk2(arg, a0, a1);
        float e0 = ex2f(a0), e1 = ex2f(a1);
        *reinterpret_cast<u32*>(out + (size_t)jj * NPIX) = f2bf2(e1, e0);
    }
}

// ---------------- softmax (pre-loop only; in-loop version fused into k_update) ----------------
__global__ void k_softmax() {
    int t = blockIdx.x * blockDim.x + threadIdx.x;
    if (t >= NB * NPIX) return;
    int b = t / NPIX, n = t % NPIX;
    const float* q = g_q + (size_t)b * NC * NPIX + n;
    float v[NC];
    float mx = -1e30f;
#pragma unroll
    for (int c = 0; c < NC; c++) { v[c] = q[c * NPIX]; mx = fmaxf(mx, v[c]); }
    float s = 0.0f;
#pragma unroll
    for (int c = 0; c < NC; c++) { v[c] = __expf(v[c] - mx); s += v[c]; }
    float inv = 1.0f / s;
    float* o = g_sm + (size_t)b * NC2 * NPIX + n;
#pragma unroll
    for (int c = 0; c < NC; c++) o[c * NPIX] = v[c] * inv;
    o[NC * NPIX] = 1.0f;
}

// separable spatial filtering: x pass then y pass (exact 96-tap Gaussian)
__global__ void k_convx() {
    __shared__ float srow[HDIM], sg[HDIM];
    int r = blockIdx.x;            // (b*NC + c)*HDIM + y
    int t = threadIdx.x;           // x
    int y = r % HDIM;
    int bc = r / HDIM;
    int c = bc % NC, b = bc / NC;
    srow[t] = g_sm[((size_t)(b * NC2 + c)) * NPIX + y * HDIM + t];
    sg[t] = g_gk[t];
    __syncthreads();
    float s = 0.0f;
#pragma unroll 8
    for (int xp = 0; xp < HDIM; xp++) s += srow[xp] * sg[abs(t - xp)];
    g_t1[(size_t)bc * NPIX + y * HDIM + t] = s;
}

__global__ void k_convy() {
    __shared__ float sg[HDIM];
    int r = blockIdx.x;            // (b*NC + c)*HDIM + y_out
    int t = threadIdx.x;           // x
    int yo = r % HDIM;
    int bc = r / HDIM;
    sg[t] = g_gk[t];
    __syncthreads();
    const float* in = g_t1 + (size_t)bc * NPIX + t;
    float s = 0.0f;
#pragma unroll 8
    for (int yp = 0; yp < HDIM; yp++) s += in[yp * HDIM] * sg[abs(yo - yp)];
    g_sp[(size_t)bc * NPIX + yo * HDIM + t] = s;
}

// ---------------- bilateral GEMM over bf16 Kb ----------------
// bl_part[s][b][c][i] = sum_{j in split s} sm[c,j]*Kb[j,i]
// per j per thread: 1 LDG.64 (4 bf16) + 2 unpack + 22 broadcast LDS.64 + 44 FFMA2.
__global__ __launch_bounds__(256, 2) void k_gemm() {
    __shared__ u64 s_pk[NC2 * JCHUNK];  // 16.9 KB, pre-packed {v,v}
    int i0 = blockIdx.x * ITILE + threadIdx.x * 4;
    int sp = blockIdx.y;
    int b  = blockIdx.z;
    const __nv_bfloat16* kb_base = g_Kbh + (size_t)b * NPIX * NPIX;
    u64 acc[NC2][2];
#pragma unroll
    for (int c = 0; c < NC2; c++) { acc[c][0] = 0ull; acc[c][1] = 0ull; }
    int jbase0 = sp * JLEN;
    for (int ch = 0; ch < NCHUNK; ch++) {
        int jbase = jbase0 + ch * JCHUNK;
        __syncthreads();
        for (int idx = threadIdx.x; idx < NC2 * JCHUNK; idx += 256) {
            int c = idx / JCHUNK, jj = idx % JCHUNK;
            u32 bits = __float_as_uint(g_sm[((size_t)(b * NC2 + c)) * NPIX + jbase + jj]);
            s_pk[idx] = ((u64)bits << 32) | bits;  // {v, v}
        }
        __syncthreads();
        const __nv_bfloat16* p = kb_base + (size_t)jbase * NPIX + i0;
#pragma unroll 2
        for (int jj = 0; jj < JCHUNK; jj++) {
            u64 raw = *reinterpret_cast<const u64*>(p);
            p += NPIX;
            u64 kx = bf2f2((u32)raw);
            u64 ky = bf2f2((u32)(raw >> 32));
#pragma unroll
            for (int c = 0; c < NC2; c++) {
                u64 sv = s_pk[c * JCHUNK + jj];
                acc[c][0] = ffma2(sv, kx, acc[c][0]);
                acc[c][1] = ffma2(sv, ky, acc[c][1]);
            }
        }
    }
#pragma unroll
    for (int c = 0; c < NC2; c++) {
        float4 v;
        v.x = __uint_as_float((u32)(acc[c][0]));
        v.y = __uint_as_float((u32)(acc[c][0] >> 32));
        v.z = __uint_as_float((u32)(acc[c][1]));
        v.w = __uint_as_float((u32)(acc[c][1] >> 32));
        *reinterpret_cast<float4*>(
            &g_part[(((size_t)sp * NB + b) * NC2 + c) * NPIX + i0]) = v;
    }
}

// reduce split-K partials, normalize, folded message weights, update q, FUSED softmax
__global__ __launch_bounds__(256) void k_update() {
    __shared__ float sA1[NC * NC], sA2[NC * NC];
    for (int i = threadIdx.x; i < NC * NC; i += 256) { sA1[i] = g_A1[i]; sA2[i] = g_A2[i]; }
    __syncthreads();
    int t = blockIdx.x * 256 + threadIdx.x;  // 0 .. 2N-1
    int b = t / NPIX, n = t % NPIX;
    float bl[NC];
    float bn = 0.0f;
#pragma unroll
    for (int c = 0; c < NC; c++) bl[c] = 0.0f;
    for (int s = 0; s < SPLITS; s++) {
        const float* pp = g_part + ((size_t)(s * NB + b)) * NC2 * NPIX + n;
#pragma unroll
        for (int c = 0; c < NC; c++) bl[c] += pp[c * NPIX];
        bn += pp[NC * NPIX];
    }
    float inv_bn = 1.0f / bn;
    float inv_sn = 1.0f / (g_snrow[n / HDIM] * g_snrow[n % HDIM]);
    float spv[NC];
    const float* spp = g_sp + (size_t)b * NC * NPIX + n;
#pragma unroll
    for (int c = 0; c < NC; c++) {
        spv[c] = spp[c * NPIX] * inv_sn;
        bl[c] *= inv_bn;
    }
    const float* up = g_u + (size_t)b * NC * NPIX + n;
    float* qp = g_q + (size_t)b * NC * NPIX + n;
    float qv[NC];
    float mx = -1e30f;
    for (int c = 0; c < NC; c++) {
        float a = up[c * NPIX];
#pragma unroll
        for (int c2 = 0; c2 < NC; c2++)
            a -= sA1[c * NC + c2] * spv[c2] + sA2[c * NC + c2] * bl[c2];
        qp[c * NPIX] = a;
        qv[c] = a;
        mx = fmaxf(mx, a);
    }
    // fused softmax -> g_sm for next iteration
    float s = 0.0f;
#pragma unroll
    for (int c = 0; c < NC; c++) { qv[c] = __expf(qv[c] - mx); s += qv[c]; }
    float inv = 1.0f / s;
    float* o = g_sm + (size_t)b * NC2 * NPIX + n;
#pragma unroll
    for (int c = 0; c < NC; c++) o[c * NPIX] = qv[c] * inv;
    o[NC * NPIX] = 1.0f;
}

// q [B,C,N] -> out [B,H,W,C]
__global__ void k_final(float* __restrict__ out) {
    int t = blockIdx.x * blockDim.x + threadIdx.x;
    if (t >= NB * NPIX * NC) return;
    int c = t % NC;
    int bn_ = t / NC;
    int n = bn_ % NPIX, b = bn_ / NPIX;
    out[t] = g_q[((size_t)b * NC + c) * NPIX + n];
}

// ---------------- launch ----------------
extern "C" void kernel_launch(void* const* d_in, const int* in_sizes, int n_in,
                              void* d_out, int out_size) {
    const float* unary = (const float*)d_in[0];  // [2,96,96,21]
    const float* rgb   = (const float*)d_in[1];  // [2,96,96,3]
    const float* Wsp   = (const float*)d_in[2];  // [21,21]
    const float* Wbp   = (const float*)d_in[3];  // [21,21]
    const float* Mp    = (const float*)d_in[4];  // [21,21]

    k_tables<<<1, HDIM>>>();
    k_mm<<<1, 448>>>(Wsp, Wbp, Mp);
    k_init_u<<<(NB * NC * NPIX + 255) / 256, 256>>>(unary);
    k_build<<<dim3(NPIX / 512, NPIX / 32, NB), 256>>>(rgb);
    k_softmax<<<(NB * NPIX + 255) / 256, 256>>>();

    for (int it = 0; it < 5; it++) {
        k_convx<<<NB * NC * HDIM, HDIM>>>();
        k_convy<<<NB * NC * HDIM, HDIM>>>();
        k_gemm<<<dim3(NPIX / ITILE, SPLITS, NB), 256>>>();
        k_update<<<NB * NPIX / 256, 256>>>();
    }
    k_final<<<(NB * NPIX * NC + 255) / 256, 256>>>((float*)d_out);
}

// round 7
// speedup vs baseline: 2.7872x; 2.7495x over previous
#include <cuda_runtime.h>
#include <cuda_bf16.h>
#include <cstdint>

typedef unsigned int u32;
typedef unsigned long long u64;

#define HDIM   96
#define NPIX   9216
#define NC     21
#define NROW   32            // padded B rows: 21 classes + ones + 10 zero
#define NB     2
#define KCH    128           // K (j) per pipeline stage
#define NCHUNKS (NPIX / KCH) // 72
#define MTILE  128
#define NTILES (NPIX / MTILE) // 72
#define A_STB  (MTILE * KCH * 2)   // 32768 B per stage
#define B_STB  (NROW  * KCH * 2)   // 8192 B per stage
#define SMEM_B_OFF (3 * A_STB)
#define SMEM_DYN   (SMEM_B_OFF + 3 * B_STB)  // 122880 B

// ---------------- device globals ----------------
__device__ __nv_bfloat16 g_Kbh[(size_t)NB * NPIX * NPIX]; // 340 MB, symmetric per batch
__device__ __nv_bfloat16 g_smh[2][NB][NROW][NPIX];        // ping-pong softmax (bf16)
__device__ float g_u [NB * NC * NPIX];
__device__ float g_q [NB * NC * NPIX];
__device__ float g_t1[NB * NC * NPIX];
__device__ float g_sp[NB * NC * NPIX];
__device__ float g_gk[HDIM];
__device__ float g_snrow[HDIM];
__device__ float g_A1[NC * NC];
__device__ float g_A2[NC * NC];

// ---------------- helpers ----------------
__device__ __forceinline__ u32 smem_u32(const void* p) {
    u32 a;
    asm("{ .reg .u64 t; cvta.to.shared.u64 t, %1; cvt.u32.u64 %0, t; }" : "=r"(a) : "l"(p));
    return a;
}
__device__ __forceinline__ void cp16(u32 dst, const void* src) {
    asm volatile("cp.async.cg.shared.global [%0], [%1], 16;" :: "r"(dst), "l"(src) : "memory");
}
__device__ __forceinline__ void ldm_x4(u32 addr, u32& r0, u32& r1, u32& r2, u32& r3) {
    asm volatile("ldmatrix.sync.aligned.m8n8.x4.shared.b16 {%0,%1,%2,%3}, [%4];"
                 : "=r"(r0), "=r"(r1), "=r"(r2), "=r"(r3) : "r"(addr));
}
__device__ __forceinline__ void mma16816(float* d, u32 a0, u32 a1, u32 a2, u32 a3,
                                         u32 b0, u32 b1) {
    asm volatile(
        "mma.sync.aligned.m16n8k16.row.col.f32.bf16.bf16.f32 "
        "{%0,%1,%2,%3}, {%4,%5,%6,%7}, {%8,%9}, {%0,%1,%2,%3};"
        : "+f"(d[0]), "+f"(d[1]), "+f"(d[2]), "+f"(d[3])
        : "r"(a0), "r"(a1), "r"(a2), "r"(a3), "r"(b0), "r"(b1));
}

// packed f32x2 helpers (build kernel)
__device__ __forceinline__ u64 ffma2(u64 a, u64 b, u64 c) {
    u64 d; asm("fma.rn.f32x2 %0, %1, %2, %3;" : "=l"(d) : "l"(a), "l"(b), "l"(c)); return d;
}
__device__ __forceinline__ u64 fadd2(u64 a, u64 b) {
    u64 d; asm("add.rn.f32x2 %0, %1, %2;" : "=l"(d) : "l"(a), "l"(b)); return d;
}
__device__ __forceinline__ u64 fmul2(u64 a, u64 b) {
    u64 d; asm("mul.rn.f32x2 %0, %1, %2;" : "=l"(d) : "l"(a), "l"(b)); return d;
}
__device__ __forceinline__ u64 pk2(float lo, float hi) {
    u64 r; asm("mov.b64 %0, {%1, %2};" : "=l"(r) : "f"(lo), "f"(hi)); return r;
}
__device__ __forceinline__ void upk2(u64 v, float& lo, float& hi) {
    asm("mov.b64 {%0, %1}, %2;" : "=f"(lo), "=f"(hi) : "l"(v));
}
__device__ __forceinline__ float ex2f(float x) {
    float y; asm("ex2.approx.f32 %0, %1;" : "=f"(y) : "f"(x)); return y;
}
__device__ __forceinline__ u32 f2bf2(float hi, float lo) {
    u32 r; asm("cvt.rn.bf16x2.f32 %0, %1, %2;" : "=r"(r) : "f"(hi), "f"(lo)); return r;
}

// ---------------- init kernels ----------------
__global__ void k_tables() {
    int t = threadIdx.x;
    g_gk[t] = __expf(-(float)(t * t) * (1.0f / 18.0f));
    __syncthreads();
    float s = 0.0f;
    for (int y2 = 0; y2 < HDIM; y2++) s += g_gk[abs(t - y2)];
    g_snrow[t] = s;
}

__global__ void k_mm(const float* __restrict__ Wsp, const float* __restrict__ Wbp,
                     const float* __restrict__ Mp) {
    int t = threadIdx.x;
    if (t >= NC * NC) return;
    int c = t / NC, c2 = t % NC;
    float a1 = 0.0f, a2 = 0.0f;
    for (int k = 0; k < NC; k++) {
        float m = Mp[c * NC + k];
        a1 += m * Wsp[k * NC + c2];
        a2 += m * Wbp[k * NC + c2];
    }
    g_A1[t] = a1;
    g_A2[t] = a2;
}

__global__ void k_init_u(const float* __restrict__ unary) {
    int t = blockIdx.x * blockDim.x + threadIdx.x;
    if (t >= NB * NC * NPIX) return;
    int n = t % NPIX;
    int bc = t / NPIX;
    int c = bc % NC, b = bc / NC;
    float v = unary[((size_t)(b * NPIX + n)) * NC + c];
    g_u[t] = v;
    g_q[t] = v;
}

// rows 21 (ones) and 22..31 (zeros) of both smh buffers; constant across iterations
__global__ void k_init_smh() {
    int t = blockIdx.x * blockDim.x + threadIdx.x;
    int total = 2 * NB * (NROW - NC) * NPIX;
    if (t >= total) return;
    int n = t % NPIX;
    int rr = t / NPIX;
    int r = rr % (NROW - NC) + NC;
    int b = (rr / (NROW - NC)) % NB;
    int buf = rr / ((NROW - NC) * NB);
    g_smh[buf][b][r][n] = __float2bfloat16(r == NC ? 1.0f : 0.0f);
}

// ---------------- build dense bilateral kernel (bf16, packed f32x2) ----------------
__global__ __launch_bounds__(256) void k_build(const float* __restrict__ rgb) {
    __shared__ u64 snj[5][32];
    int b  = blockIdx.z;
    int i0 = (blockIdx.x * 256 + threadIdx.x) * 2;
    int j0 = blockIdx.y * 32;
    if (threadIdx.x < 32) {
        int j = j0 + threadIdx.x;
        const float* rp = rgb + ((size_t)(b * NPIX + j)) * 3;
        float vy = -(float)(j / HDIM) * (1.0f / 160.0f);
        float vx = -(float)(j % HDIM) * (1.0f / 160.0f);
        float vr = -rp[0] * (1.0f / 3.0f);
        float vg = -rp[1] * (1.0f / 3.0f);
        float vb = -rp[2] * (1.0f / 3.0f);
        snj[0][threadIdx.x] = pk2(vy, vy);
        snj[1][threadIdx.x] = pk2(vx, vx);
        snj[2][threadIdx.x] = pk2(vr, vr);
        snj[3][threadIdx.x] = pk2(vg, vg);
        snj[4][threadIdx.x] = pk2(vb, vb);
    }
    __syncthreads();
    const float* rp0 = rgb + ((size_t)(b * NPIX + i0)) * 3;
    u64 fy = pk2((float)(i0 / HDIM) * (1.0f / 160.0f), (float)((i0 + 1) / HDIM) * (1.0f / 160.0f));
    u64 fx = pk2((float)(i0 % HDIM) * (1.0f / 160.0f), (float)((i0 + 1) % HDIM) * (1.0f / 160.0f));
    u64 fr = pk2(rp0[0] * (1.0f / 3.0f), rp0[3] * (1.0f / 3.0f));
    u64 fg = pk2(rp0[1] * (1.0f / 3.0f), rp0[4] * (1.0f / 3.0f));
    u64 fb = pk2(rp0[2] * (1.0f / 3.0f), rp0[5] * (1.0f / 3.0f));
    const float m05l2e = -0.7213475204444817f;
    u64 cm = pk2(m05l2e, m05l2e);
    __nv_bfloat16* out = g_Kbh + (size_t)b * NPIX * NPIX + (size_t)j0 * NPIX + i0;
#pragma unroll 4
    for (int jj = 0; jj < 32; jj++) {
        u64 d, acc;
        d = fadd2(fy, snj[0][jj]); acc = fmul2(d, d);
        d = fadd2(fx, snj[1][jj]); acc = ffma2(d, d, acc);
        d = fadd2(fr, snj[2][jj]); acc = ffma2(d, d, acc);
        d = fadd2(fg, snj[3][jj]); acc = ffma2(d, d, acc);
        d = fadd2(fb, snj[4][jj]); acc = ffma2(d, d, acc);
        u64 arg = fmul2(acc, cm);
        float a0, a1; upk2(arg, a0, a1);
        *reinterpret_cast<u32*>(out + (size_t)jj * NPIX) = f2bf2(ex2f(a1), ex2f(a0));
    }
}

// initial softmax of unary -> smh buffer 0
__global__ void k_softmax0() {
    int t = blockIdx.x * blockDim.x + threadIdx.x;
    if (t >= NB * NPIX) return;
    int b = t / NPIX, n = t % NPIX;
    const float* q = g_q + (size_t)b * NC * NPIX + n;
    float v[NC];
    float mx = -1e30f;
#pragma unroll
    for (int c = 0; c < NC; c++) { v[c] = q[c * NPIX]; mx = fmaxf(mx, v[c]); }
    float s = 0.0f;
#pragma unroll
    for (int c = 0; c < NC; c++) { v[c] = __expf(v[c] - mx); s += v[c]; }
    float inv = 1.0f / s;
#pragma unroll
    for (int c = 0; c < NC; c++) g_smh[0][b][c][n] = __float2bfloat16(v[c] * inv);
}

// ---------------- separable spatial filtering ----------------
__global__ void k_convx(int cur) {
    __shared__ float srow[HDIM], sg[HDIM];
    int r = blockIdx.x;
    int t = threadIdx.x;
    int y = r % HDIM;
    int bc = r / HDIM;
    int c = bc % NC, b = bc / NC;
    srow[t] = __bfloat162float(g_smh[cur][b][c][y * HDIM + t]);
    sg[t] = g_gk[t];
    __syncthreads();
    float s = 0.0f;
#pragma unroll 8
    for (int xp = 0; xp < HDIM; xp++) s += srow[xp] * sg[abs(t - xp)];
    g_t1[(size_t)bc * NPIX + y * HDIM + t] = s;
}

__global__ void k_convy() {
    __shared__ float sg[HDIM];
    int r = blockIdx.x;
    int t = threadIdx.x;
    int yo = r % HDIM;
    int bc = r / HDIM;
    sg[t] = g_gk[t];
    __syncthreads();
    const float* in = g_t1 + (size_t)bc * NPIX + t;
    float s = 0.0f;
#pragma unroll 8
    for (int yp = 0; yp < HDIM; yp++) s += in[yp * HDIM] * sg[abs(yo - yp)];
    g_sp[(size_t)bc * NPIX + yo * HDIM + t] = s;
}

// ---------------- stage loader: gmem -> swizzled smem via cp.async ----------------
// A rows (128) and B rows (32) are 256 B; 16B unit u stored at (u ^ (r&7)).
__device__ __forceinline__ void load_chunk(u32 sb, int st, int jb,
                                           const __nv_bfloat16* kb,
                                           const __nv_bfloat16* bh, int tid) {
    u32 ab = sb + st * A_STB;
#pragma unroll
    for (int v = 0; v < 8; v++) {
        int t = tid + v * 256;
        int r = t >> 4, u = t & 15;
        cp16(ab + r * 256 + ((u ^ (r & 7)) << 4),
             (const char*)(kb + (size_t)r * NPIX + jb) + u * 16);
    }
    u32 bb = sb + SMEM_B_OFF + st * B_STB;
#pragma unroll
    for (int v = 0; v < 2; v++) {
        int t = tid + v * 256;
        int r = t >> 4, u = t & 15;
        cp16(bb + r * 256 + ((u ^ (r & 7)) << 4),
             (const char*)(bh + (size_t)r * NPIX + jb) + u * 16);
    }
    asm volatile("cp.async.commit_group;" ::: "memory");
}

// ---------------- HMMA GEMM + fused normalize/update/softmax epilogue ----------------
__global__ __launch_bounds__(256, 1) void k_gemm(int cur) {
    extern __shared__ __align__(1024) char smem[];
    __shared__ float sA1[NC * NC], sA2[NC * NC];

    int tid  = threadIdx.x;
    int warp = tid >> 5, lane = tid & 31;
    int b    = blockIdx.y;
    int i0   = blockIdx.x * MTILE;
    u32 sb   = smem_u32(smem);
    int nxt  = cur ^ 1;

    for (int i = tid; i < NC * NC; i += 256) { sA1[i] = g_A1[i]; sA2[i] = g_A2[i]; }

    const __nv_bfloat16* kb = g_Kbh + (size_t)b * NPIX * NPIX + (size_t)i0 * NPIX; // symmetric
    const __nv_bfloat16* bh = &g_smh[cur][b][0][0];

    load_chunk(sb, 0, 0 * KCH, kb, bh, tid);
    load_chunk(sb, 1, 1 * KCH, kb, bh, tid);
    load_chunk(sb, 2, 2 * KCH, kb, bh, tid);

    float acc[4][4];
#pragma unroll
    for (int nt = 0; nt < 4; nt++)
#pragma unroll
        for (int r = 0; r < 4; r++) acc[nt][r] = 0.0f;

    // per-lane ldmatrix geometry
    int a_row = warp * 16 + ((lane >> 3) & 1) * 8 + (lane & 7);
    int a_ku  = lane >> 4;                    // 0 or 1 (+ kk*2)
    int b_n   = ((lane >> 4) & 1) * 8 + (lane & 7);
    int b_ku  = (lane >> 3) & 1;

    for (int ch = 0; ch < NCHUNKS; ch++) {
        int st = ch % 3;
        if (ch < NCHUNKS - 2)       asm volatile("cp.async.wait_group 2;" ::: "memory");
        else if (ch == NCHUNKS - 2) asm volatile("cp.async.wait_group 1;" ::: "memory");
        else                        asm volatile("cp.async.wait_group 0;" ::: "memory");
        __syncthreads();

        u32 a_base  = sb + st * A_STB + a_row * 256;
        u32 b_base0 = sb + SMEM_B_OFF + st * B_STB + b_n * 256;
        u32 b_base1 = b_base0 + 16 * 256;
        int a_sw = a_row & 7, b_sw = b_n & 7;

#pragma unroll
        for (int kk = 0; kk < 8; kk++) {
            u32 a0, a1, a2, a3, p0, p1, p2, p3, q0, q1, q2, q3;
            ldm_x4(a_base  + (((kk * 2 + a_ku) ^ a_sw) << 4), a0, a1, a2, a3);
            ldm_x4(b_base0 + (((kk * 2 + b_ku) ^ b_sw) << 4), p0, p1, p2, p3);
            ldm_x4(b_base1 + (((kk * 2 + b_ku) ^ b_sw) << 4), q0, q1, q2, q3);
            mma16816(acc[0], a0, a1, a2, a3, p0, p1);
            mma16816(acc[1], a0, a1, a2, a3, p2, p3);
            mma16816(acc[2], a0, a1, a2, a3, q0, q1);
            mma16816(acc[3], a0, a1, a2, a3, q2, q3);
        }
        __syncthreads();
        if (ch + 3 < NCHUNKS) load_chunk(sb, st, (ch + 3) * KCH, kb, bh, tid);
    }

    // ---- transpose accumulators to smem (stride 33 floats: conflict-free) ----
    __syncthreads();
    float* tr = (float*)smem;   // 128*33*4 = 16.9 KB, stages are dead now
    {
        int r0 = warp * 16 + (lane >> 2);
        int cb = (lane & 3) * 2;
#pragma unroll
        for (int nt = 0; nt < 4; nt++) {
            tr[r0 * 33 + nt * 8 + cb]            = acc[nt][0];
            tr[r0 * 33 + nt * 8 + cb + 1]        = acc[nt][1];
            tr[(r0 + 8) * 33 + nt * 8 + cb]      = acc[nt][2];
            tr[(r0 + 8) * 33 + nt * 8 + cb + 1]  = acc[nt][3];
        }
    }
    __syncthreads();

    // ---- epilogue: threads 0-127, one pixel each ----
    if (tid < MTILE) {
        const float* row = tr + tid * 33;
        int i = i0 + tid;
        float inv_bn = 1.0f / row[NC];                    // ones channel
        float inv_sn = 1.0f / (g_snrow[i / HDIM] * g_snrow[i % HDIM]);
        float spv[NC], blv[NC];
        const float* spp = g_sp + (size_t)b * NC * NPIX + i;
#pragma unroll
        for (int c = 0; c < NC; c++) {
            spv[c] = spp[c * NPIX] * inv_sn;
            blv[c] = row[c] * inv_bn;
        }
        const float* up = g_u + (size_t)b * NC * NPIX + i;
        float* qp = g_q + (size_t)b * NC * NPIX + i;
        float qv[NC];
        float mx = -1e30f;
        for (int c = 0; c < NC; c++) {
            float a = up[c * NPIX];
#pragma unroll
            for (int c2 = 0; c2 < NC; c2++)
                a -= sA1[c * NC + c2] * spv[c2] + sA2[c * NC + c2] * blv[c2];
            qp[c * NPIX] = a;
            qv[c] = a;
            mx = fmaxf(mx, a);
        }
        float s = 0.0f;
#pragma unroll
        for (int c = 0; c < NC; c++) { qv[c] = __expf(qv[c] - mx); s += qv[c]; }
        float inv = 1.0f / s;
#pragma unroll
        for (int c = 0; c < NC; c++)
            g_smh[nxt][b][c][i] = __float2bfloat16(qv[c] * inv);
    }
}

// q [B,C,N] -> out [B,H,W,C]
__global__ void k_final(float* __restrict__ out) {
    int t = blockIdx.x * blockDim.x + threadIdx.x;
    if (t >= NB * NPIX * NC) return;
    int c = t % NC;
    int bn_ = t / NC;
    int n = bn_ % NPIX, b = bn_ / NPIX;
    out[t] = g_q[((size_t)b * NC + c) * NPIX + n];
}

// ---------------- launch ----------------
extern "C" void kernel_launch(void* const* d_in, const int* in_sizes, int n_in,
                              void* d_out, int out_size) {
    const float* unary = (const float*)d_in[0];
    const float* rgb   = (const float*)d_in[1];
    const float* Wsp   = (const float*)d_in[2];
    const float* Wbp   = (const float*)d_in[3];
    const float* Mp    = (const float*)d_in[4];

    cudaFuncSetAttribute(k_gemm, cudaFuncAttributeMaxDynamicSharedMemorySize, SMEM_DYN);

    k_tables<<<1, HDIM>>>();
    k_mm<<<1, 448>>>(Wsp, Wbp, Mp);
    k_init_u<<<(NB * NC * NPIX + 255) / 256, 256>>>(unary);
    k_init_smh<<<(2 * NB * (NROW - NC) * NPIX + 255) / 256, 256>>>();
    k_build<<<dim3(NPIX / 512, NPIX / 32, NB), 256>>>(rgb);
    k_softmax0<<<(NB * NPIX + 255) / 256, 256>>>();

    for (int it = 0; it < 5; it++) {
        int cur = it & 1;
        k_convx<<<NB * NC * HDIM, HDIM>>>(cur);
        k_convy<<<NB * NC * HDIM, HDIM>>>();
        k_gemm<<<dim3(NTILES, NB), 256, SMEM_DYN>>>(cur);
    }
    k_final<<<(NB * NPIX * NC + 255) / 256, 256>>>((float*)d_out);
}

// round 8
// speedup vs baseline: 2.7971x; 1.0036x over previous
#include <cuda_runtime.h>
#include <cuda_bf16.h>
#include <cstdint>

typedef unsigned int u32;
typedef unsigned long long u64;

#define HDIM   96
#define NPIX   9216
#define NC     21
#define NROW   32            // padded B rows: 21 classes + ones + 10 zero
#define NB     2
#define KCH    128           // K (j) per pipeline stage
#define NCHUNKS (NPIX / KCH) // 72
#define NSTG   4
#define MTILE  128
#define NTILES (NPIX / MTILE) // 72
#define A_STB  (MTILE * KCH * 2)   // 32768 B per stage
#define B_STB  (NROW  * KCH * 2)   // 8192 B per stage
#define SMEM_B_OFF (NSTG * A_STB)          // 131072
#define SMEM_DYN   (SMEM_B_OFF + NSTG * B_STB)  // 163840 B
#define CONV_SMEM  ((2 * NPIX + HDIM) * 4)      // 74112 B

// ---------------- device globals ----------------
__device__ __nv_bfloat16 g_Kbh[(size_t)NB * NPIX * NPIX]; // 340 MB, symmetric per batch
__device__ __nv_bfloat16 g_smh[2][NB][NROW][NPIX];        // ping-pong softmax (bf16)
__device__ float g_u [NB * NC * NPIX];
__device__ float g_sp[NB * NC * NPIX];
__device__ float g_gk[HDIM];
__device__ float g_snrow[HDIM];
__device__ float g_A1[NC * NC];
__device__ float g_A2[NC * NC];

// ---------------- helpers ----------------
__device__ __forceinline__ u32 smem_u32(const void* p) {
    u32 a;
    asm("{ .reg .u64 t; cvta.to.shared.u64 t, %1; cvt.u32.u64 %0, t; }" : "=r"(a) : "l"(p));
    return a;
}
__device__ __forceinline__ void cp16(u32 dst, const void* src) {
    asm volatile("cp.async.cg.shared.global [%0], [%1], 16;" :: "r"(dst), "l"(src) : "memory");
}
__device__ __forceinline__ void ldm_x4(u32 addr, u32& r0, u32& r1, u32& r2, u32& r3) {
    asm volatile("ldmatrix.sync.aligned.m8n8.x4.shared.b16 {%0,%1,%2,%3}, [%4];"
                 : "=r"(r0), "=r"(r1), "=r"(r2), "=r"(r3) : "r"(addr));
}
__device__ __forceinline__ void mma16816(float* d, u32 a0, u32 a1, u32 a2, u32 a3,
                                         u32 b0, u32 b1) {
    asm volatile(
        "mma.sync.aligned.m16n8k16.row.col.f32.bf16.bf16.f32 "
        "{%0,%1,%2,%3}, {%4,%5,%6,%7}, {%8,%9}, {%0,%1,%2,%3};"
        : "+f"(d[0]), "+f"(d[1]), "+f"(d[2]), "+f"(d[3])
        : "r"(a0), "r"(a1), "r"(a2), "r"(a3), "r"(b0), "r"(b1));
}

// packed f32x2 helpers (build kernel)
__device__ __forceinline__ u64 ffma2(u64 a, u64 b, u64 c) {
    u64 d; asm("fma.rn.f32x2 %0, %1, %2, %3;" : "=l"(d) : "l"(a), "l"(b), "l"(c)); return d;
}
__device__ __forceinline__ u64 fadd2(u64 a, u64 b) {
    u64 d; asm("add.rn.f32x2 %0, %1, %2;" : "=l"(d) : "l"(a), "l"(b)); return d;
}
__device__ __forceinline__ u64 fmul2(u64 a, u64 b) {
    u64 d; asm("mul.rn.f32x2 %0, %1, %2;" : "=l"(d) : "l"(a), "l"(b)); return d;
}
__device__ __forceinline__ u64 pk2(float lo, float hi) {
    u64 r; asm("mov.b64 %0, {%1, %2};" : "=l"(r) : "f"(lo), "f"(hi)); return r;
}
__device__ __forceinline__ void upk2(u64 v, float& lo, float& hi) {
    asm("mov.b64 {%0, %1}, %2;" : "=f"(lo), "=f"(hi) : "l"(v));
}
__device__ __forceinline__ float ex2f(float x) {
    float y; asm("ex2.approx.f32 %0, %1;" : "=f"(y) : "f"(x)); return y;
}
__device__ __forceinline__ u32 f2bf2(float hi, float lo) {
    u32 r; asm("cvt.rn.bf16x2.f32 %0, %1, %2;" : "=r"(r) : "f"(hi), "f"(lo)); return r;
}

// ---------------- init kernels ----------------
__global__ void k_tables() {
    int t = threadIdx.x;
    g_gk[t] = __expf(-(float)(t * t) * (1.0f / 18.0f));
    __syncthreads();
    float s = 0.0f;
    for (int y2 = 0; y2 < HDIM; y2++) s += g_gk[abs(t - y2)];
    g_snrow[t] = s;
}

__global__ void k_mm(const float* __restrict__ Wsp, const float* __restrict__ Wbp,
                     const float* __restrict__ Mp) {
    int t = threadIdx.x;
    if (t >= NC * NC) return;
    int c = t / NC, c2 = t % NC;
    float a1 = 0.0f, a2 = 0.0f;
    for (int k = 0; k < NC; k++) {
        float m = Mp[c * NC + k];
        a1 += m * Wsp[k * NC + c2];
        a2 += m * Wbp[k * NC + c2];
    }
    g_A1[t] = a1;
    g_A2[t] = a2;
}

__global__ void k_init_u(const float* __restrict__ unary) {
    int t = blockIdx.x * blockDim.x + threadIdx.x;
    if (t >= NB * NC * NPIX) return;
    int n = t % NPIX;
    int bc = t / NPIX;
    int c = bc % NC, b = bc / NC;
    g_u[t] = unary[((size_t)(b * NPIX + n)) * NC + c];
}

// rows 21 (ones) and 22..31 (zeros) of both smh buffers; constant across iterations
__global__ void k_init_smh() {
    int t = blockIdx.x * blockDim.x + threadIdx.x;
    int total = 2 * NB * (NROW - NC) * NPIX;
    if (t >= total) return;
    int n = t % NPIX;
    int rr = t / NPIX;
    int r = rr % (NROW - NC) + NC;
    int b = (rr / (NROW - NC)) % NB;
    int buf = rr / ((NROW - NC) * NB);
    g_smh[buf][b][r][n] = __float2bfloat16(r == NC ? 1.0f : 0.0f);
}

// ---------------- build dense bilateral kernel (bf16, packed f32x2) ----------------
__global__ __launch_bounds__(256) void k_build(const float* __restrict__ rgb) {
    __shared__ u64 snj[5][32];
    int b  = blockIdx.z;
    int i0 = (blockIdx.x * 256 + threadIdx.x) * 2;
    int j0 = blockIdx.y * 32;
    if (threadIdx.x < 32) {
        int j = j0 + threadIdx.x;
        const float* rp = rgb + ((size_t)(b * NPIX + j)) * 3;
        float vy = -(float)(j / HDIM) * (1.0f / 160.0f);
        float vx = -(float)(j % HDIM) * (1.0f / 160.0f);
        float vr = -rp[0] * (1.0f / 3.0f);
        float vg = -rp[1] * (1.0f / 3.0f);
        float vb = -rp[2] * (1.0f / 3.0f);
        snj[0][threadIdx.x] = pk2(vy, vy);
        snj[1][threadIdx.x] = pk2(vx, vx);
        snj[2][threadIdx.x] = pk2(vr, vr);
        snj[3][threadIdx.x] = pk2(vg, vg);
        snj[4][threadIdx.x] = pk2(vb, vb);
    }
    __syncthreads();
    const float* rp0 = rgb + ((size_t)(b * NPIX + i0)) * 3;
    u64 fy = pk2((float)(i0 / HDIM) * (1.0f / 160.0f), (float)((i0 + 1) / HDIM) * (1.0f / 160.0f));
    u64 fx = pk2((float)(i0 % HDIM) * (1.0f / 160.0f), (float)((i0 + 1) % HDIM) * (1.0f / 160.0f));
    u64 fr = pk2(rp0[0] * (1.0f / 3.0f), rp0[3] * (1.0f / 3.0f));
    u64 fg = pk2(rp0[1] * (1.0f / 3.0f), rp0[4] * (1.0f / 3.0f));
    u64 fb = pk2(rp0[2] * (1.0f / 3.0f), rp0[5] * (1.0f / 3.0f));
    const float m05l2e = -0.7213475204444817f;
    u64 cm = pk2(m05l2e, m05l2e);
    __nv_bfloat16* out = g_Kbh + (size_t)b * NPIX * NPIX + (size_t)j0 * NPIX + i0;
#pragma unroll 4
    for (int jj = 0; jj < 32; jj++) {
        u64 d, acc;
        d = fadd2(fy, snj[0][jj]); acc = fmul2(d, d);
        d = fadd2(fx, snj[1][jj]); acc = ffma2(d, d, acc);
        d = fadd2(fr, snj[2][jj]); acc = ffma2(d, d, acc);
        d = fadd2(fg, snj[3][jj]); acc = ffma2(d, d, acc);
        d = fadd2(fb, snj[4][jj]); acc = ffma2(d, d, acc);
        u64 arg = fmul2(acc, cm);
        float a0, a1; upk2(arg, a0, a1);
        *reinterpret_cast<u32*>(out + (size_t)jj * NPIX) = f2bf2(ex2f(a1), ex2f(a0));
    }
}

// initial softmax of unary -> smh buffer 0
__global__ void k_softmax0() {
    int t = blockIdx.x * blockDim.x + threadIdx.x;
    if (t >= NB * NPIX) return;
    int b = t / NPIX, n = t % NPIX;
    const float* q = g_u + (size_t)b * NC * NPIX + n;
    float v[NC];
    float mx = -1e30f;
#pragma unroll
    for (int c = 0; c < NC; c++) { v[c] = q[c * NPIX]; mx = fmaxf(mx, v[c]); }
    float s = 0.0f;
#pragma unroll
    for (int c = 0; c < NC; c++) { v[c] = __expf(v[c] - mx); s += v[c]; }
    float inv = 1.0f / s;
#pragma unroll
    for (int c = 0; c < NC; c++) g_smh[0][b][c][n] = __float2bfloat16(v[c] * inv);
}

// ---------------- fused separable spatial filter (x then y pass, one kernel) ----------------
// one block per (b,c) plane; block (96,4); 8-row register blocking.
__global__ __launch_bounds__(384) void k_conv(int cur) {
    extern __shared__ float cs[];           // pl[9216] | bl[9216] | sg[96]
    float* pl = cs;
    float* bl = cs + NPIX;
    float* sg = cs + 2 * NPIX;
    int tid = threadIdx.y * HDIM + threadIdx.x;
    int c = blockIdx.x % NC, b = blockIdx.x / NC;
    const __nv_bfloat16* src = &g_smh[cur][b][c][0];
    for (int idx = tid; idx < NPIX; idx += 384) pl[idx] = __bfloat162float(src[idx]);
    if (tid < HDIM) sg[tid] = g_gk[tid];
    __syncthreads();
    int x = threadIdx.x, yg = threadIdx.y;
    // x-pass: out(y,x) = sum_xp pl[y][xp] * g[|x-xp|]
#pragma unroll
    for (int grp = 0; grp < 3; grp++) {
        int yb = yg * 24 + grp * 8;
        float a[8];
#pragma unroll
        for (int r = 0; r < 8; r++) a[r] = 0.0f;
        for (int xp = 0; xp < HDIM; xp++) {
            float gv = sg[abs(x - xp)];
#pragma unroll
            for (int r = 0; r < 8; r++) a[r] += pl[(yb + r) * HDIM + xp] * gv;
        }
#pragma unroll
        for (int r = 0; r < 8; r++) bl[(yb + r) * HDIM + x] = a[r];
    }
    __syncthreads();
    // y-pass: sp(yo,x) = sum_yp bl[yp][x] * g[|yo-yp|]
    float* out = g_sp + (size_t)(b * NC + c) * NPIX;
#pragma unroll
    for (int grp = 0; grp < 3; grp++) {
        int yb = yg * 24 + grp * 8;
        float a[8];
#pragma unroll
        for (int r = 0; r < 8; r++) a[r] = 0.0f;
        for (int yp = 0; yp < HDIM; yp++) {
            float v = bl[yp * HDIM + x];
#pragma unroll
            for (int r = 0; r < 8; r++) a[r] += v * sg[abs(yb + r - yp)];
        }
#pragma unroll
        for (int r = 0; r < 8; r++) out[(yb + r) * HDIM + x] = a[r];
    }
}

// ---------------- stage loader: gmem -> swizzled smem via cp.async ----------------
__device__ __forceinline__ void load_chunk(u32 sb, int st, int jb,
                                           const __nv_bfloat16* kb,
                                           const __nv_bfloat16* bh, int tid) {
    u32 ab = sb + st * A_STB;
#pragma unroll
    for (int v = 0; v < 8; v++) {
        int t = tid + v * 256;
        int r = t >> 4, u = t & 15;
        cp16(ab + r * 256 + ((u ^ (r & 7)) << 4),
             (const char*)(kb + (size_t)r * NPIX + jb) + u * 16);
    }
    u32 bb = sb + SMEM_B_OFF + st * B_STB;
#pragma unroll
    for (int v = 0; v < 2; v++) {
        int t = tid + v * 256;
        int r = t >> 4, u = t & 15;
        cp16(bb + r * 256 + ((u ^ (r & 7)) << 4),
             (const char*)(bh + (size_t)r * NPIX + jb) + u * 16);
    }
    asm volatile("cp.async.commit_group;" ::: "memory");
}

// ---------------- HMMA GEMM + fused normalize/update/softmax epilogue ----------------
__global__ __launch_bounds__(256, 1) void k_gemm(int cur, int last, float* __restrict__ outp) {
    extern __shared__ __align__(1024) char smem[];
    __shared__ float sA1[NC * NC], sA2[NC * NC];

    int tid  = threadIdx.x;
    int warp = tid >> 5, lane = tid & 31;
    int b    = blockIdx.y;
    int i0   = blockIdx.x * MTILE;
    u32 sb   = smem_u32(smem);
    int nxt  = cur ^ 1;

    for (int i = tid; i < NC * NC; i += 256) { sA1[i] = g_A1[i]; sA2[i] = g_A2[i]; }

    const __nv_bfloat16* kb = g_Kbh + (size_t)b * NPIX * NPIX + (size_t)i0 * NPIX; // symmetric
    const __nv_bfloat16* bh = &g_smh[cur][b][0][0];

#pragma unroll
    for (int s = 0; s < NSTG; s++) load_chunk(sb, s, s * KCH, kb, bh, tid);

    float acc[4][4];
#pragma unroll
    for (int nt = 0; nt < 4; nt++)
#pragma unroll
        for (int r = 0; r < 4; r++) acc[nt][r] = 0.0f;

    int a_row = warp * 16 + ((lane >> 3) & 1) * 8 + (lane & 7);
    int a_ku  = lane >> 4;
    int b_n   = ((lane >> 4) & 1) * 8 + (lane & 7);
    int b_ku  = (lane >> 3) & 1;

    for (int ch = 0; ch < NCHUNKS; ch++) {
        int st = ch & (NSTG - 1);
        int rem = NCHUNKS - 1 - ch;
        if (rem >= 3)      asm volatile("cp.async.wait_group 3;" ::: "memory");
        else if (rem == 2) asm volatile("cp.async.wait_group 2;" ::: "memory");
        else if (rem == 1) asm volatile("cp.async.wait_group 1;" ::: "memory");
        else               asm volatile("cp.async.wait_group 0;" ::: "memory");
        __syncthreads();

        u32 a_base  = sb + st * A_STB + a_row * 256;
        u32 b_base0 = sb + SMEM_B_OFF + st * B_STB + b_n * 256;
        u32 b_base1 = b_base0 + 16 * 256;
        int a_sw = a_row & 7, b_sw = b_n & 7;

#pragma unroll
        for (int kk = 0; kk < 8; kk++) {
            u32 a0, a1, a2, a3, p0, p1, p2, p3, q0, q1, q2, q3;
            ldm_x4(a_base  + (((kk * 2 + a_ku) ^ a_sw) << 4), a0, a1, a2, a3);
            ldm_x4(b_base0 + (((kk * 2 + b_ku) ^ b_sw) << 4), p0, p1, p2, p3);
            ldm_x4(b_base1 + (((kk * 2 + b_ku) ^ b_sw) << 4), q0, q1, q2, q3);
            mma16816(acc[0], a0, a1, a2, a3, p0, p1);
            mma16816(acc[1], a0, a1, a2, a3, p2, p3);
            mma16816(acc[2], a0, a1, a2, a3, q0, q1);
            mma16816(acc[3], a0, a1, a2, a3, q2, q3);
        }
        __syncthreads();
        if (ch + NSTG < NCHUNKS) load_chunk(sb, st, (ch + NSTG) * KCH, kb, bh, tid);
    }

    // ---- transpose accumulators to smem (stride 33 floats: conflict-free) ----
    __syncthreads();
    float* tr = (float*)smem;   // stages are dead now
    {
        int r0 = warp * 16 + (lane >> 2);
        int cb = (lane & 3) * 2;
#pragma unroll
        for (int nt = 0; nt < 4; nt++) {
            tr[r0 * 33 + nt * 8 + cb]            = acc[nt][0];
            tr[r0 * 33 + nt * 8 + cb + 1]        = acc[nt][1];
            tr[(r0 + 8) * 33 + nt * 8 + cb]      = acc[nt][2];
            tr[(r0 + 8) * 33 + nt * 8 + cb + 1]  = acc[nt][3];
        }
    }
    __syncthreads();

    // ---- epilogue: threads 0-127, one pixel each ----
    if (tid < MTILE) {
        const float* row = tr + tid * 33;
        int i = i0 + tid;
        float inv_bn = 1.0f / row[NC];                    // ones channel
        float inv_sn = 1.0f / (g_snrow[i / HDIM] * g_snrow[i % HDIM]);
        float spv[NC], blv[NC];
        const float* spp = g_sp + (size_t)b * NC * NPIX + i;
#pragma unroll
        for (int c = 0; c < NC; c++) {
            spv[c] = spp[c * NPIX] * inv_sn;
            blv[c] = row[c] * inv_bn;
        }
        const float* up = g_u + (size_t)b * NC * NPIX + i;
        float qv[NC];
        float mx = -1e30f;
        for (int c = 0; c < NC; c++) {
            float a = up[c * NPIX];
#pragma unroll
            for (int c2 = 0; c2 < NC; c2++)
                a -= sA1[c * NC + c2] * spv[c2] + sA2[c * NC + c2] * blv[c2];
            qv[c] = a;
            mx = fmaxf(mx, a);
        }
        if (last) {
            float* op = outp + ((size_t)(b * NPIX + i)) * NC;
#pragma unroll
            for (int c = 0; c < NC; c++) op[c] = qv[c];
        } else {
            float s = 0.0f;
#pragma unroll
            for (int c = 0; c < NC; c++) { qv[c] = __expf(qv[c] - mx); s += qv[c]; }
            float inv = 1.0f / s;
#pragma unroll
            for (int c = 0; c < NC; c++)
                g_smh[nxt][b][c][i] = __float2bfloat16(qv[c] * inv);
        }
    }
}

// ---------------- launch ----------------
extern "C" void kernel_launch(void* const* d_in, const int* in_sizes, int n_in,
                              void* d_out, int out_size) {
    const float* unary = (const float*)d_in[0];
    const float* rgb   = (const float*)d_in[1];
    const float* Wsp   = (const float*)d_in[2];
    const float* Wbp   = (const float*)d_in[3];
    const float* Mp    = (const float*)d_in[4];

    cudaFuncSetAttribute(k_gemm, cudaFuncAttributeMaxDynamicSharedMemorySize, SMEM_DYN);
    cudaFuncSetAttribute(k_conv, cudaFuncAttributeMaxDynamicSharedMemorySize, CONV_SMEM);

    k_tables<<<1, HDIM>>>();
    k_mm<<<1, 448>>>(Wsp, Wbp, Mp);
    k_init_u<<<(NB * NC * NPIX + 255) / 256, 256>>>(unary);
    k_init_smh<<<(2 * NB * (NROW - NC) * NPIX + 255) / 256, 256>>>();
    k_build<<<dim3(NPIX / 512, NPIX / 32, NB), 256>>>(rgb);
    k_softmax0<<<(NB * NPIX + 255) / 256, 256>>>();

    for (int it = 0; it < 5; it++) {
        int cur = it & 1;
        k_conv<<<NB * NC, dim3(HDIM, 4), CONV_SMEM>>>(cur);
        k_gemm<<<dim3(NTILES, NB), 256, SMEM_DYN>>>(cur, it == 4, (float*)d_out);
    }
}